// round 1
// baseline (speedup 1.0000x reference)
#include <cuda_runtime.h>
#include <math.h>

// Problem constants (B=128 trees, depth D=6, NPT=127)
#define Hh     450
#define NNODE  16256   // 128*127
#define NEDGE  32256   // 2*128*126
#define BM 64
#define BN 64
#define BK 16

// Scratch (static device globals; allocation-free kernel_launch)
__device__ float g_x  [NNODE*Hh];
__device__ float g_Xz [NNODE*Hh];
__device__ float g_Xh [NNODE*Hh];
__device__ float g_Xr [NNODE*Hh];
__device__ float g_Xg [NNODE*Hh];
__device__ float g_m  [NEDGE*Hh];
__device__ float g_rm [NEDGE*Hh];
__device__ float g_nm [NNODE*Hh];
__device__ float g_nrm[NNODE*Hh];

__device__ __forceinline__ float sigmoidf_(float v){ return 1.0f/(1.0f+expf(-v)); }

// ---------------------------------------------------------------------------
// init: gather embeddings, zero node accumulators
// ---------------------------------------------------------------------------
__global__ void k_init(const int* __restrict__ wid, const float* __restrict__ emb){
  int idx = blockIdx.x*blockDim.x + threadIdx.x;
  if (idx < NNODE*Hh){
    int r = idx / Hh, c = idx - r*Hh;
    g_x[idx]   = emb[wid[r]*Hh + c];
    g_nm[idx]  = 0.f;
    g_nrm[idx] = 0.f;
  }
}

// ---------------------------------------------------------------------------
// Precompute GEMM: C(which) = g_x @ B + bias   (M=NNODE, N=K=450)
// which: 0->g_Xz 1->g_Xh 2->g_Xr 3->g_Xg
// ---------------------------------------------------------------------------
__global__ __launch_bounds__(256) void k_gemm_bias(
    const float* __restrict__ B, const float* __restrict__ bias, int which){
  __shared__ float As[BK][BM];
  __shared__ float Bs[BK][BN];
  float* C = (which==0)?g_Xz:(which==1)?g_Xh:(which==2)?g_Xr:g_Xg;
  int bm = blockIdx.x*BM, bn = blockIdx.y*BN;
  int tid = threadIdx.x;
  int ty = tid>>4, tx = tid&15;
  float acc[4][4] = {};
  int lr = tid>>2;          // A tile row 0..63
  int lk = (tid&3)*4;       // A tile k offset 0,4,8,12
  const float* Arow = g_x + (size_t)(bm+lr)*Hh;   // M multiple of 64 -> always valid
  int kr = tid>>5;          // B tile row 0..7 (+8)
  int nc = (tid&31)*2;      // B tile col (even)

  for (int k0=0; k0<Hh; k0+=BK){
    #pragma unroll
    for (int u=0;u<2;u++){
      int kk = lk + u*2, gk = k0 + kk;
      float2 v = make_float2(0.f,0.f);
      if (gk < Hh) v = *(const float2*)(Arow + gk);
      As[kk][lr] = v.x; As[kk+1][lr] = v.y;
    }
    #pragma unroll
    for (int u=0;u<2;u++){
      int k = kr + u*8, gk = k0 + k, gn = bn + nc;
      float2 v = make_float2(0.f,0.f);
      if (gk < Hh && gn < Hh) v = *(const float2*)(B + (size_t)gk*Hh + gn);
      Bs[k][nc] = v.x; Bs[k][nc+1] = v.y;
    }
    __syncthreads();
    #pragma unroll
    for (int kk=0; kk<BK; kk++){
      float a[4], b[4];
      #pragma unroll
      for (int i=0;i<4;i++) a[i] = As[kk][ty*4+i];
      #pragma unroll
      for (int j=0;j<4;j++) b[j] = Bs[kk][tx*4+j];
      #pragma unroll
      for (int i=0;i<4;i++)
        #pragma unroll
        for (int j=0;j<4;j++) acc[i][j] = fmaf(a[i], b[j], acc[i][j]);
    }
    __syncthreads();
  }
  #pragma unroll
  for (int i=0;i<4;i++){
    int r = bm + ty*4 + i;
    #pragma unroll
    for (int j=0;j<4;j++){
      int c = bn + tx*4 + j;
      if (c < Hh) C[(size_t)r*Hh + c] = acc[i][j] + bias[c];
    }
  }
}

// ---------------------------------------------------------------------------
// Level 0 (deepest leaves): s = arm = 0  ->  m_new = sigmoid(Xz[se]) * tanh(Xh[se])
// ---------------------------------------------------------------------------
__global__ void k_lvl0(const int* __restrict__ sched, const int* __restrict__ srcv){
  int e  = sched[blockIdx.x];
  int se = srcv[e];
  const float* xz = g_Xz + (size_t)se*Hh;
  const float* xh = g_Xh + (size_t)se*Hh;
  float* mo = g_m + (size_t)e*Hh;
  for (int c = threadIdx.x; c < Hh; c += blockDim.x)
    mo[c] = sigmoidf_(xz[c]) * tanhf(xh[c]);
}

// ---------------------------------------------------------------------------
// GEMM A (dual): Z = S @ WzB, MT = ARM @ WhB, fused gather + GRU epilogue.
//   S[r]   = node_m[src[e]]  - (sub ? m[rev[e]]  : 0)
//   ARM[r] = node_rm[src[e]] - (sub ? rm[rev[e]] : 0)
//   m_new = (1-z)*s + z*mt ; write g_m[e]
// Ne is always a multiple of 64 -> no row guards.
// ---------------------------------------------------------------------------
__global__ __launch_bounds__(256) void k_gemmA(
    const int* __restrict__ sched, const int* __restrict__ srcv,
    const int* __restrict__ revv,
    const float* __restrict__ WzB, const float* __restrict__ WhB, int sub){
  __shared__ float Ss[BK][BM], Rs[BK][BM];
  __shared__ float Bz[BK][BN], Bh[BK][BN];
  __shared__ int s_eid[BM], s_se[BM], s_rv[BM];
  int bm = blockIdx.x*BM, bn = blockIdx.y*BN;
  int tid = threadIdx.x;
  if (tid < BM){
    int e = sched[bm + tid];
    s_eid[tid] = e;
    s_se[tid]  = srcv[e];
    s_rv[tid]  = revv[e];
  }
  __syncthreads();
  int ty = tid>>4, tx = tid&15;
  float accZ[4][4] = {}, accH[4][4] = {};
  int lr = tid>>2, lk = (tid&3)*4;
  const float* nmrow = g_nm  + (size_t)s_se[lr]*Hh;
  const float* nrrow = g_nrm + (size_t)s_se[lr]*Hh;
  const float* mrow  = g_m   + (size_t)s_rv[lr]*Hh;
  const float* rmrow = g_rm  + (size_t)s_rv[lr]*Hh;
  int kr = tid>>5, nc = (tid&31)*2;

  for (int k0=0; k0<Hh; k0+=BK){
    #pragma unroll
    for (int u=0;u<2;u++){
      int kk = lk + u*2, gk = k0 + kk;
      float2 vm = make_float2(0.f,0.f), vr = make_float2(0.f,0.f);
      if (gk < Hh){
        vm = *(const float2*)(nmrow + gk);
        vr = *(const float2*)(nrrow + gk);
        if (sub){
          float2 a = *(const float2*)(mrow  + gk);
          float2 b = *(const float2*)(rmrow + gk);
          vm.x -= a.x; vm.y -= a.y; vr.x -= b.x; vr.y -= b.y;
        }
      }
      Ss[kk][lr] = vm.x; Ss[kk+1][lr] = vm.y;
      Rs[kk][lr] = vr.x; Rs[kk+1][lr] = vr.y;
    }
    #pragma unroll
    for (int u=0;u<2;u++){
      int k = kr + u*8, gk = k0 + k, gn = bn + nc;
      float2 vz = make_float2(0.f,0.f), vh = make_float2(0.f,0.f);
      if (gk < Hh && gn < Hh){
        vz = *(const float2*)(WzB + (size_t)gk*Hh + gn);
        vh = *(const float2*)(WhB + (size_t)gk*Hh + gn);
      }
      Bz[k][nc] = vz.x; Bz[k][nc+1] = vz.y;
      Bh[k][nc] = vh.x; Bh[k][nc+1] = vh.y;
    }
    __syncthreads();
    #pragma unroll
    for (int kk=0; kk<BK; kk++){
      float as[4], ar[4], vbz[4], vbh[4];
      #pragma unroll
      for (int i=0;i<4;i++){ as[i]=Ss[kk][ty*4+i]; ar[i]=Rs[kk][ty*4+i]; }
      #pragma unroll
      for (int j=0;j<4;j++){ vbz[j]=Bz[kk][tx*4+j]; vbh[j]=Bh[kk][tx*4+j]; }
      #pragma unroll
      for (int i=0;i<4;i++)
        #pragma unroll
        for (int j=0;j<4;j++){
          accZ[i][j] = fmaf(as[i], vbz[j], accZ[i][j]);
          accH[i][j] = fmaf(ar[i], vbh[j], accH[i][j]);
        }
    }
    __syncthreads();
  }
  #pragma unroll
  for (int i=0;i<4;i++){
    int r  = ty*4 + i;
    int se = s_se[r], e = s_eid[r], rv = s_rv[r];
    const float* xz = g_Xz + (size_t)se*Hh;
    const float* xh = g_Xh + (size_t)se*Hh;
    const float* nm = g_nm + (size_t)se*Hh;
    const float* mr = g_m  + (size_t)rv*Hh;
    float* mo = g_m + (size_t)e*Hh;
    #pragma unroll
    for (int j=0;j<4;j++){
      int c = bn + tx*4 + j;
      if (c >= Hh) continue;
      float z  = sigmoidf_(accZ[i][j] + xz[c]);
      float mt = tanhf   (accH[i][j] + xh[c]);
      float s  = nm[c] - (sub ? mr[c] : 0.f);
      mo[c] = (1.f - z)*s + z*mt;
    }
  }
}

// ---------------------------------------------------------------------------
// GEMM B: R = m_new @ Ur, epilogue: r=sigmoid(R + Xr[dst]); rm = r*m_new;
// write g_rm[e]; deterministic (non-atomic) scatter into node_m / node_rm:
//   up levels: sibling edge pairs at even-aligned adjacent rows share dst
//              -> both rows live in the same thread's microtile, sum locally.
//   down levels: dst unique per edge in the level.
// ---------------------------------------------------------------------------
__global__ __launch_bounds__(256) void k_gemmB(
    const int* __restrict__ sched, const int* __restrict__ dstv,
    const float* __restrict__ Ur, int up){
  __shared__ float As[BK][BM], Bs[BK][BN];
  __shared__ int s_eid[BM], s_de[BM];
  int bm = blockIdx.x*BM, bn = blockIdx.y*BN;
  int tid = threadIdx.x;
  if (tid < BM){
    int e = sched[bm + tid];
    s_eid[tid] = e;
    s_de[tid]  = dstv[e];
  }
  __syncthreads();
  int ty = tid>>4, tx = tid&15;
  float acc[4][4] = {};
  int lr = tid>>2, lk = (tid&3)*4;
  const float* Arow = g_m + (size_t)s_eid[lr]*Hh;
  int kr = tid>>5, nc = (tid&31)*2;

  for (int k0=0; k0<Hh; k0+=BK){
    #pragma unroll
    for (int u=0;u<2;u++){
      int kk = lk + u*2, gk = k0 + kk;
      float2 v = make_float2(0.f,0.f);
      if (gk < Hh) v = *(const float2*)(Arow + gk);
      As[kk][lr] = v.x; As[kk+1][lr] = v.y;
    }
    #pragma unroll
    for (int u=0;u<2;u++){
      int k = kr + u*8, gk = k0 + k, gn = bn + nc;
      float2 v = make_float2(0.f,0.f);
      if (gk < Hh && gn < Hh) v = *(const float2*)(Ur + (size_t)gk*Hh + gn);
      Bs[k][nc] = v.x; Bs[k][nc+1] = v.y;
    }
    __syncthreads();
    #pragma unroll
    for (int kk=0; kk<BK; kk++){
      float a[4], b[4];
      #pragma unroll
      for (int i=0;i<4;i++) a[i] = As[kk][ty*4+i];
      #pragma unroll
      for (int j=0;j<4;j++) b[j] = Bs[kk][tx*4+j];
      #pragma unroll
      for (int i=0;i<4;i++)
        #pragma unroll
        for (int j=0;j<4;j++) acc[i][j] = fmaf(a[i], b[j], acc[i][j]);
    }
    __syncthreads();
  }
  #pragma unroll
  for (int j=0;j<4;j++){
    int c = bn + tx*4 + j;
    if (c >= Hh) continue;
    float mvv[4], rmvv[4];
    #pragma unroll
    for (int i=0;i<4;i++){
      int r = ty*4 + i;
      int e = s_eid[r], de = s_de[r];
      float mv  = g_m[(size_t)e*Hh + c];
      float rr  = sigmoidf_(acc[i][j] + g_Xr[(size_t)de*Hh + c]);
      float rmv = rr * mv;
      g_rm[(size_t)e*Hh + c] = rmv;
      mvv[i] = mv; rmvv[i] = rmv;
    }
    if (up){
      #pragma unroll
      for (int i=0;i<4;i+=2){
        int de = s_de[ty*4 + i];     // sibling pair shares dst
        size_t idx = (size_t)de*Hh + c;
        g_nm[idx]  += mvv[i]  + mvv[i+1];
        g_nrm[idx] += rmvv[i] + rmvv[i+1];
      }
    } else {
      #pragma unroll
      for (int i=0;i<4;i++){
        int de = s_de[ty*4 + i];
        size_t idx = (size_t)de*Hh + c;
        g_nm[idx]  += mvv[i];
        g_nrm[idx] += rmvv[i];
      }
    }
  }
}

// ---------------------------------------------------------------------------
// Final readout: out = relu(Xg + node_m @ WgB)   (M=NNODE)
// ---------------------------------------------------------------------------
__global__ __launch_bounds__(256) void k_final(
    const float* __restrict__ WgB, float* __restrict__ out){
  __shared__ float As[BK][BM], Bs[BK][BN];
  int bm = blockIdx.x*BM, bn = blockIdx.y*BN;
  int tid = threadIdx.x;
  int ty = tid>>4, tx = tid&15;
  float acc[4][4] = {};
  int lr = tid>>2, lk = (tid&3)*4;
  const float* Arow = g_nm + (size_t)(bm+lr)*Hh;
  int kr = tid>>5, nc = (tid&31)*2;

  for (int k0=0; k0<Hh; k0+=BK){
    #pragma unroll
    for (int u=0;u<2;u++){
      int kk = lk + u*2, gk = k0 + kk;
      float2 v = make_float2(0.f,0.f);
      if (gk < Hh) v = *(const float2*)(Arow + gk);
      As[kk][lr] = v.x; As[kk+1][lr] = v.y;
    }
    #pragma unroll
    for (int u=0;u<2;u++){
      int k = kr + u*8, gk = k0 + k, gn = bn + nc;
      float2 v = make_float2(0.f,0.f);
      if (gk < Hh && gn < Hh) v = *(const float2*)(WgB + (size_t)gk*Hh + gn);
      Bs[k][nc] = v.x; Bs[k][nc+1] = v.y;
    }
    __syncthreads();
    #pragma unroll
    for (int kk=0; kk<BK; kk++){
      float a[4], b[4];
      #pragma unroll
      for (int i=0;i<4;i++) a[i] = As[kk][ty*4+i];
      #pragma unroll
      for (int j=0;j<4;j++) b[j] = Bs[kk][tx*4+j];
      #pragma unroll
      for (int i=0;i<4;i++)
        #pragma unroll
        for (int j=0;j<4;j++) acc[i][j] = fmaf(a[i], b[j], acc[i][j]);
    }
    __syncthreads();
  }
  #pragma unroll
  for (int i=0;i<4;i++){
    int r = bm + ty*4 + i;
    #pragma unroll
    for (int j=0;j<4;j++){
      int c = bn + tx*4 + j;
      if (c < Hh)
        out[(size_t)r*Hh + c] = fmaxf(acc[i][j] + g_Xg[(size_t)r*Hh + c], 0.f);
    }
  }
}

// ---------------------------------------------------------------------------
// kernel_launch
// Inputs: 0 wid, 1 src, 2 dst, 3 rev, 4 sched, 5 emb, 6 Wz, 7 bz,
//         8 Wr, 9 Ur, 10 bur, 11 Wh, 12 bh, 13 Wg, 14 bg
// ---------------------------------------------------------------------------
extern "C" void kernel_launch(void* const* d_in, const int* in_sizes, int n_in,
                              void* d_out, int out_size) {
  const int*   wid   = (const int*)  d_in[0];
  const int*   srcv  = (const int*)  d_in[1];
  const int*   dstv  = (const int*)  d_in[2];
  const int*   revv  = (const int*)  d_in[3];
  const int*   sched = (const int*)  d_in[4];
  const float* emb   = (const float*)d_in[5];
  const float* Wz    = (const float*)d_in[6];
  const float* bz    = (const float*)d_in[7];
  const float* Wr    = (const float*)d_in[8];
  const float* Ur    = (const float*)d_in[9];
  const float* bur   = (const float*)d_in[10];
  const float* Wh    = (const float*)d_in[11];
  const float* bh    = (const float*)d_in[12];
  const float* Wg    = (const float*)d_in[13];
  const float* bg    = (const float*)d_in[14];
  float* out = (float*)d_out;

  const int lmax = in_sizes[4] / 12;   // 8192
  static const int NeTab[12] = {8192,4096,2048,1024,512,256,
                                 256,512,1024,2048,4096,8192};

  // init + precompute
  k_init<<<(NNODE*Hh + 255)/256, 256>>>(wid, emb);
  dim3 gpre(NNODE/BM, (Hh + BN - 1)/BN);
  k_gemm_bias<<<gpre, 256>>>(Wz, bz,  0);   // Xz = x@Wz_top + bz
  k_gemm_bias<<<gpre, 256>>>(Wh, bh,  1);   // Xh = x@Wh_top + bh
  k_gemm_bias<<<gpre, 256>>>(Wr, bur, 2);   // Xr = x@Wr     + bur
  k_gemm_bias<<<gpre, 256>>>(Wg, bg,  3);   // Xg = x@Wg_top + bg

  // level 0 (s = arm = 0): pointwise m_new, then R-GEMM + scatter
  k_lvl0<<<NeTab[0], 256>>>(sched, srcv);
  {
    dim3 g(NeTab[0]/BM, (Hh + BN - 1)/BN);
    k_gemmB<<<g, 256>>>(sched, dstv, Ur, 1);
  }
  // levels 1..11
  for (int lvl = 1; lvl < 12; lvl++) {
    int Ne  = NeTab[lvl];
    int sub = (lvl >= 6) ? 1 : 0;     // downward pass: subtract reverse message
    int up  = (lvl <  6) ? 1 : 0;
    dim3 g(Ne/BM, (Hh + BN - 1)/BN);
    k_gemmA<<<g, 256>>>(sched + lvl*lmax, srcv, revv,
                        Wz + Hh*Hh, Wh + Hh*Hh, sub);
    k_gemmB<<<g, 256>>>(sched + lvl*lmax, dstv, Ur, up);
  }

  // readout
  dim3 gf(NNODE/BM, (Hh + BN - 1)/BN);
  k_final<<<gf, 256>>>(Wg + Hh*Hh, out);
}